// round 2
// baseline (speedup 1.0000x reference)
#include <cuda_runtime.h>
#include <cuda_bf16.h>

// Problem constants (fixed by the reference)
#define NB      2
#define NX      200
#define NY      200
#define NZ      16     // Z == HEIGHT, h = 1 -> bin index == z
#define NC      17
#define NCHOOSE 4000
#define NHEIGHT 16
#define EMPTY_LAB 16
#define LOG_RATIO (-1.0986122886681098f)   // log(MIN_W/MAX_W) = log(1/3)

#define CPB   16                 // columns per block in loss kernel
#define NBLK  (NB * NCHOOSE / CPB)   // 500

// Persistent scratch (device globals are zero-initialized at load)
__device__ float g_weights[NB * NHEIGHT];
__device__ float g_sum[NB];
__device__ float g_nval[NB];
__device__ int   g_ticket;

// ================================================================ K1
// Single block: init scratch, count valid labels per (b,z) with
// register-private histograms, reduce, compute weights.
__global__ __launch_bounds__(1024, 1)
void hv_count_weights_k(const int* __restrict__ labels,
                        const int* __restrict__ sel) {
    __shared__ int s_cnt[NB * NHEIGHT];
    int t = threadIdx.x;

    if (t == 0) g_ticket = 0;
    if (t < NB) { g_sum[t] = 0.0f; g_nval[t] = 0.0f; }
    if (t < NB * NHEIGHT) s_cnt[t] = 0;
    __syncthreads();

    // threads [0,512) -> batch 0, [512,1024) -> batch 1
    int b  = t >> 9;
    int s0 = t & 511;

    // Prefetch all sel pairs first (break the sel->labels dependency chain)
    int base[8];
    #pragma unroll
    for (int k = 0; k < 8; ++k) {
        int s = s0 + (k << 9);
        if (s < NCHOOSE) {
            int col = b * NCHOOSE + s;
            int x = sel[2 * col];
            int y = sel[2 * col + 1];
            base[k] = ((b * NX + x) * NY + y) << 4;   // voxel index
        } else {
            base[k] = -1;
        }
    }

    int cnt[NHEIGHT];
    #pragma unroll
    for (int i = 0; i < NHEIGHT; ++i) cnt[i] = 0;

    #pragma unroll
    for (int k = 0; k < 8; ++k) {
        if (base[k] >= 0) {
            const int4* lp = (const int4*)(labels + base[k]);
            #pragma unroll
            for (int q = 0; q < 4; ++q) {
                int4 v = lp[q];
                if (v.x != EMPTY_LAB) cnt[q * 4 + 0]++;
                if (v.y != EMPTY_LAB) cnt[q * 4 + 1]++;
                if (v.z != EMPTY_LAB) cnt[q * 4 + 2]++;
                if (v.w != EMPTY_LAB) cnt[q * 4 + 3]++;
            }
        }
    }

    // Warp-reduce each bin (batch is uniform within a warp)
    #pragma unroll
    for (int i = 0; i < NHEIGHT; ++i) {
        int v = cnt[i];
        #pragma unroll
        for (int o = 16; o >= 1; o >>= 1)
            v += __shfl_xor_sync(0xffffffffu, v, o);
        if ((t & 31) == 0 && v) atomicAdd(&s_cnt[b * NHEIGHT + i], v);
    }
    __syncthreads();

    // Weights: 32 threads, max over each batch's 16 bins via shfl in halves
    if (t < NB * NHEIGHT) {
        float c = (float)s_cnt[t];
        float mc = c;
        #pragma unroll
        for (int o = 1; o < 16; o <<= 1)
            mc = fmaxf(mc, __shfl_xor_sync(0xffffffffu, mc, o));
        mc = fmaxf(mc, 1.0f);
        g_weights[t] = (c > 0.0f) ? 3.0f * __expf(LOG_RATIO * (c / mc)) : 0.0f;
    }
}

// ================================================================ K2
// 500 blocks x 256 threads. Each block stages 16 columns (16*1088B) of
// preds into shared via coalesced float4 loads, then thread-per-voxel
// softmax/loss, warp+block reduction, 2 atomics, last-block finalize.
__global__ __launch_bounds__(256, 4)
void hv_loss_k(const float* __restrict__ preds,
               const int*   __restrict__ labels,
               const int*   __restrict__ sel,
               float* __restrict__ out) {
    __shared__ float s_pred[CPB * NZ * NC];   // 16*272 floats = 17408 B
    __shared__ int   s_lab[CPB * NZ];
    __shared__ int   s_base[CPB];
    __shared__ float s_w[NHEIGHT];
    __shared__ float s_psum[8];
    __shared__ float s_pn[8];

    int t = threadIdx.x;
    int blk = blockIdx.x;
    int b = (blk >= NBLK / NB) ? 1 : 0;       // 250 blocks per batch

    if (t < CPB) {
        int col = blk * CPB + t;
        int x = sel[2 * col];
        int y = sel[2 * col + 1];
        s_base[t] = ((b * NX + x) * NY + y) << 4;
    }
    if (t < NHEIGHT) s_w[t] = g_weights[b * NHEIGHT + t];
    __syncthreads();

    // Stage preds: 16 columns * 68 float4 = 1088 float4 loads
    #pragma unroll
    for (int i = 0; i < 5; ++i) {
        int f = t + i * 256;
        if (f < CPB * 68) {
            int c   = f / 68;
            int idx = f - c * 68;
            const float4* src =
                (const float4*)preds + ((size_t)s_base[c] * NC >> 2);
            ((float4*)s_pred)[f] = src[idx];
        }
    }
    // Stage labels: one per thread
    {
        int c = t >> 4, z = t & 15;
        s_lab[t] = labels[s_base[c] + z];
    }
    __syncthreads();

    // Per-voxel loss
    int c = t >> 4, z = t & 15;
    int lab = s_lab[t];
    float sl = 0.0f, val = 0.0f;
    if (lab != EMPTY_LAB) {
        const float* v = &s_pred[c * (NZ * NC) + z * NC];
        float m = v[0];
        #pragma unroll
        for (int k = 1; k < NC; ++k) m = fmaxf(m, v[k]);
        float sum = 0.0f;
        #pragma unroll
        for (int k = 0; k < NC; ++k) sum += __expf(v[k] - m);
        float p  = __expf(v[lab] - m) / sum;
        float wl = s_w[z] * __logf(p + 0.001f);
        float ax = fabsf(wl);
        sl  = (ax < 1.0f) ? 0.5f * wl * wl : (ax - 0.5f);
        val = 1.0f;
    }

    // Warp reduce
    #pragma unroll
    for (int o = 16; o >= 1; o >>= 1) {
        sl  += __shfl_xor_sync(0xffffffffu, sl,  o);
        val += __shfl_xor_sync(0xffffffffu, val, o);
    }
    if ((t & 31) == 0) { s_psum[t >> 5] = sl; s_pn[t >> 5] = val; }
    __syncthreads();

    if (t == 0) {
        float bs = 0.0f, bn = 0.0f;
        #pragma unroll
        for (int w = 0; w < 8; ++w) { bs += s_psum[w]; bn += s_pn[w]; }
        atomicAdd(&g_sum[b],  bs);
        atomicAdd(&g_nval[b], bn);
        __threadfence();
        int ticket = atomicAdd(&g_ticket, 1);
        if (ticket == NBLK - 1) {
            float acc = 0.0f;
            #pragma unroll
            for (int bb = 0; bb < NB; ++bb)
                acc += g_sum[bb] / fmaxf(g_nval[bb], 1.0f);
            out[0] = acc / (float)NB;
        }
    }
}

// ================================================================ launch
extern "C" void kernel_launch(void* const* d_in, const int* in_sizes, int n_in,
                              void* d_out, int out_size) {
    const float* preds  = (const float*)d_in[0];
    const int*   labels = (const int*)  d_in[1];
    const int*   sel    = (const int*)  d_in[2];
    float* out = (float*)d_out;

    hv_count_weights_k<<<1, 1024>>>(labels, sel);
    hv_loss_k<<<NBLK, 256>>>(preds, labels, sel, out);
}